// round 7
// baseline (speedup 1.0000x reference)
#include <cuda_runtime.h>

// Quanvolution (2x2, 4 qubits, RY encode + RY params + CNOT ring, <Z_q>).
//
// Closed form per output pixel (x,y), patch q0=a(x,y), q1=a(x,y+1),
// q2=a(x+1,y), q3=a(x+1,y+1):
//   Zq = cos(pi*a_q + w_q)        (one MUFU.COS each, arg via FMA)
//   ch0 = Z1*Z2*Z3, ch1 = Z0*Z1, ch2 = Z0*Z1*Z2, ch3 = Z0*Z1*Z2*Z3
//
// R7: NO shared memory, NO barrier. One thread = a 4-row column strip
// (rows x0..x0+3, fixed y). Lanes map to consecutive y so all 10 LDG.32 and
// all 16 STG.32 are unit-stride coalesced. All dependency chains are private
// to the thread; latency hidden by occupancy instead of fenced per block.

#define H_IN 224
#define W_IN 224
#define L_OUT 223
#define PI_F 3.14159265358979323846f

union F2U {
    float a[2];
    unsigned long long u;
};

__device__ __forceinline__ unsigned long long mul2(unsigned long long a,
                                                   unsigned long long b) {
    unsigned long long r;
    asm("mul.rn.f32x2 %0, %1, %2;" : "=l"(r) : "l"(a), "l"(b));
    return r;
}

__global__ __launch_bounds__(224) void quanv_main_kernel(
    const float* __restrict__ in,   // (64,1,224,224)
    const float* __restrict__ w,    // (1,4)
    float* __restrict__ out)        // (64,4,223,223)
{
    const int y  = threadIdx.x;             // 0..223; lane -> consecutive y
    const int x0 = blockIdx.x * 4;          // row strip base, 0..220
    const int b  = blockIdx.y;

    if (y >= L_OUT) return;                 // tx = 223 idle (no barrier: safe)

    const float4 wv = __ldg(reinterpret_cast<const float4*>(w));  // w0..w3
    const float* inb = in + (size_t)b * (H_IN * W_IN);

    // Load column y and y+1 for rows x0..x0+4 (clamp row index: the clamped
    // row only feeds pixel j=3 of the last strip, which is never stored).
    float v0[5], v1[5];
    #pragma unroll
    for (int j = 0; j < 5; j++) {
        const int gx = (x0 + j < H_IN) ? (x0 + j) : (H_IN - 1);
        const float* rp = inb + gx * W_IN + y;
        v0[j] = __ldg(rp);
        v1[j] = __ldg(rp + 1);
    }

    // Z values: 16 independent MUFU.COS.
    float Z0[4], Z1[4], Z2[4], Z3[4];
    #pragma unroll
    for (int j = 0; j < 4; j++) {
        Z0[j] = __cosf(fmaf(v0[j],     PI_F, wv.x));   // q0 = a(x, y)
        Z1[j] = __cosf(fmaf(v1[j],     PI_F, wv.y));   // q1 = a(x, y+1)
        Z2[j] = __cosf(fmaf(v0[j + 1], PI_F, wv.z));   // q2 = a(x+1, y)
        Z3[j] = __cosf(fmaf(v1[j + 1], PI_F, wv.w));   // q3 = a(x+1, y+1)
    }

    // Channel products, packed f32x2 over row pairs (j=0,1) and (j=2,3).
    float c0[4], c1[4], c2[4], c3[4];
    #pragma unroll
    for (int h = 0; h < 2; h++) {
        F2U z0, z1, z2, z3;
        z0.a[0] = Z0[2 * h]; z0.a[1] = Z0[2 * h + 1];
        z1.a[0] = Z1[2 * h]; z1.a[1] = Z1[2 * h + 1];
        z2.a[0] = Z2[2 * h]; z2.a[1] = Z2[2 * h + 1];
        z3.a[0] = Z3[2 * h]; z3.a[1] = Z3[2 * h + 1];

        F2U p01, p23, r0, r2, r3;
        p01.u = mul2(z0.u, z1.u);           // ch1
        p23.u = mul2(z2.u, z3.u);
        r0.u  = mul2(z1.u, p23.u);          // ch0 = Z1 Z2 Z3
        r2.u  = mul2(p01.u, z2.u);          // ch2 = Z0 Z1 Z2
        r3.u  = mul2(p01.u, p23.u);         // ch3 = Z0 Z1 Z2 Z3

        #pragma unroll
        for (int k = 0; k < 2; k++) {
            const int j = 2 * h + k;
            c0[j] = r0.a[k];
            c1[j] = p01.a[k];
            c2[j] = r2.a[k];
            c3[j] = r3.a[k];
        }
    }

    // Coalesced stores: lanes = consecutive y; 4 rows x 4 channels.
    const size_t plane = (size_t)L_OUT * L_OUT;
    float* ob = out + (size_t)b * 4 * plane + (size_t)x0 * L_OUT + y;

    #pragma unroll
    for (int j = 0; j < 4; j++) {
        if (x0 + j < L_OUT) {
            ob[0]         = c0[j];
            ob[plane]     = c1[j];
            ob[2 * plane] = c2[j];
            ob[3 * plane] = c3[j];
        }
        ob += L_OUT;
    }
}

extern "C" void kernel_launch(void* const* d_in, const int* in_sizes, int n_in,
                              void* d_out, int out_size) {
    const float* inputs = (const float*)d_in[0];   // (64,1,224,224) float32
    const float* weight = (const float*)d_in[1];   // (1,4) float32
    float* out = (float*)d_out;                    // (64,4,223,223) float32

    dim3 grid((L_OUT + 3) / 4,   // 56 row strips
              64);               // batch
    quanv_main_kernel<<<grid, 224>>>(inputs, weight, out);
}

// round 8
// speedup vs baseline: 1.1124x; 1.1124x over previous
#include <cuda_runtime.h>

// Quanvolution (2x2, 4 qubits, RY encode + RY params + CNOT ring, <Z_q>).
//
//   Zq = cos(pi*a_q + w_q) = cos(pi a_q) cos w_q - sin(pi a_q) sin w_q
//   ch0 = Z1*Z2*Z3, ch1 = Z0*Z1, ch2 = Z0*Z1*Z2, ch3 = Z0*Z1*Z2*Z3
//
// R8: shared (cos,sin) tile computed ONCE per element (2 MUFU/elem = minimal),
// column-strip consumer (4 rows per thread) so each smem element is read once
// per thread and reused across qubits: smem reads drop 32 -> 20 B/px.
// Lanes map to consecutive columns: LDS and STG both coalesced.

#define H_IN 224
#define W_IN 224
#define L_OUT 223
#define TILE 32
#define HROWS 33
#define EPITCH 34          // float2 row pitch
#define PI_F 3.14159265358979323846f

__global__ __launch_bounds__(256) void quanv_main_kernel(
    const float* __restrict__ in,   // (64,1,224,224)
    const float* __restrict__ w,    // (1,4)
    float* __restrict__ out)        // (64,4,223,223)
{
    __shared__ float2 E[HROWS][EPITCH];   // (cos(pi a), sin(pi a)) per halo elem

    const int tid = threadIdx.x;
    const int b  = blockIdx.z;
    const int x0 = blockIdx.y * TILE;
    const int y0 = blockIdx.x * TILE;

    const float4 wv = __ldg(reinterpret_cast<const float4*>(w));
    float sw0, cw0, sw1, cw1, sw2, cw2, sw3, cw3;
    __sincosf(wv.x, &sw0, &cw0);
    __sincosf(wv.y, &sw1, &cw1);
    __sincosf(wv.z, &sw2, &cw2);
    __sincosf(wv.w, &sw3, &cw3);

    const float* inb = in + (size_t)b * (H_IN * W_IN);
    const int lane = tid & 31;

    // ---- Loader: cols 0..31 by lane, rows strided; clamp indices (clamped
    // elements only feed pixels that are never stored). ----
    {
        const int gy = (y0 + lane < W_IN) ? (y0 + lane) : (W_IN - 1);
        for (int r = tid >> 5; r < HROWS; r += 8) {
            const int gx = (x0 + r < H_IN) ? (x0 + r) : (H_IN - 1);
            float s, c;
            __sincosf(__ldg(&inb[gx * W_IN + gy]) * PI_F, &s, &c);
            E[r][lane] = make_float2(c, s);
        }
    }
    // ---- Col 32 ----
    if (tid < HROWS) {
        const int gx = (x0 + tid < H_IN) ? (x0 + tid) : (H_IN - 1);
        const int gy = (y0 + 32 < W_IN) ? (y0 + 32) : (W_IN - 1);
        float s, c;
        __sincosf(__ldg(&inb[gx * W_IN + gy]) * PI_F, &s, &c);
        E[tid][32] = make_float2(c, s);
    }
    __syncthreads();

    // ---- Consumer: column strip of 4 pixels (rows rb..rb+3, col c). ----
    const int c  = lane;            // lane -> consecutive y: coalesced LDS/STG
    const int rb = (tid >> 5) << 2; // 0,4,...,28
    const int y  = y0 + c;
    if (y >= L_OUT) return;

    float2 e0[5], e1[5];            // col c, col c+1: rows rb..rb+4
    #pragma unroll
    for (int j = 0; j < 5; j++) {
        e0[j] = E[rb + j][c];
        e1[j] = E[rb + j][c + 1];
    }

    const size_t plane = (size_t)L_OUT * L_OUT;
    float* o = out + (size_t)b * 4 * plane + (size_t)(x0 + rb) * L_OUT + y;
    const bool full = (x0 + rb + 3) < L_OUT;

    #pragma unroll
    for (int j = 0; j < 4; j++) {
        if (full || (x0 + rb + j) < L_OUT) {
            // q0=(r,c) q1=(r,c+1) q2=(r+1,c) q3=(r+1,c+1)
            const float Z0 = fmaf(-e0[j].y,     sw0, e0[j].x     * cw0);
            const float Z1 = fmaf(-e1[j].y,     sw1, e1[j].x     * cw1);
            const float Z2 = fmaf(-e0[j + 1].y, sw2, e0[j + 1].x * cw2);
            const float Z3 = fmaf(-e1[j + 1].y, sw3, e1[j + 1].x * cw3);

            const float p01 = Z0 * Z1;
            const float p23 = Z2 * Z3;

            o[0]         = Z1 * p23;    // ch0 = Z1 Z2 Z3
            o[plane]     = p01;         // ch1 = Z0 Z1
            o[2 * plane] = p01 * Z2;    // ch2 = Z0 Z1 Z2
            o[3 * plane] = p01 * p23;   // ch3 = Z0 Z1 Z2 Z3
        }
        o += L_OUT;
    }
}

extern "C" void kernel_launch(void* const* d_in, const int* in_sizes, int n_in,
                              void* d_out, int out_size) {
    const float* inputs = (const float*)d_in[0];   // (64,1,224,224) float32
    const float* weight = (const float*)d_in[1];   // (1,4) float32
    float* out = (float*)d_out;                    // (64,4,223,223) float32

    dim3 grid((L_OUT + TILE - 1) / TILE,   // 7
              (L_OUT + TILE - 1) / TILE,   // 7
              64);                          // batch
    quanv_main_kernel<<<grid, 256>>>(inputs, weight, out);
}

// round 9
// speedup vs baseline: 1.4320x; 1.2873x over previous
#include <cuda_runtime.h>

// Quanvolution (2x2, 4 qubits, RY encode + RY params + CNOT ring, <Z_q>).
//
//   Zq = cos(pi*a_q + w_q) = cos(pi a_q) cos w_q - sin(pi a_q) sin w_q
//   ch0 = Z1*Z2*Z3, ch1 = Z0*Z1, ch2 = Z0*Z1*Z2, ch3 = Z0*Z1*Z2*Z3
//
// R9 = R3 (best: 14.1us main) with a surgically improved loader:
//  - batched/unrolled LDGs (MLP~5) before any trig, no int division,
//    clamped indices instead of zero-fill branches,
//  - halo remainder (row 32 + col 32) in one predicated batched side pass,
//  - weight trig by 4 threads into smem under the SAME single barrier.
// Consumer / tile layout / store pattern are R3 verbatim (proven coalesced).

#define H_IN 224
#define W_IN 224
#define L_OUT 223
#define TILE 32
#define HROWS 33
#define HPAD 36            // float2 row pitch (R3-proven conflict-free)
#define PI_F 3.14159265358979323846f

__global__ __launch_bounds__(256) void quanv_main_kernel(
    const float* __restrict__ in,   // (64,1,224,224)
    const float* __restrict__ w,    // (1,4)
    float* __restrict__ out)        // (64,4,223,223)
{
    __shared__ float2 CS[HROWS][HPAD];   // (cos(pi a), sin(pi a))
    __shared__ float wtrig[8];           // cw0..cw3, sw0..sw3

    const int tid  = threadIdx.x;
    const int lane = tid & 31;
    const int wg   = tid >> 5;           // 0..7
    const int b  = blockIdx.z;
    const int x0 = blockIdx.y * TILE;
    const int y0 = blockIdx.x * TILE;

    const float* inb = in + (size_t)b * (H_IN * W_IN);

    // ---- Batched tile loads: col = lane, rows wg, wg+8, wg+16, wg+24 ----
    const int gy = (y0 + lane < W_IN) ? (y0 + lane) : (W_IN - 1);
    float v[4];
    #pragma unroll
    for (int it = 0; it < 4; it++) {
        const int r  = wg + 8 * it;
        const int gx = (x0 + r < H_IN) ? (x0 + r) : (H_IN - 1);
        v[it] = __ldg(&inb[gx * W_IN + gy]);
    }

    // ---- Halo remainder: row 32 (cols 0..32) + col 32 (rows 0..31) ----
    float ve = 0.0f;
    int er = 0, ec = 0;
    const bool extra = tid < 65;
    if (extra) {
        er = (tid < 33) ? 32 : (tid - 33);
        ec = (tid < 33) ? tid : 32;
        const int gx = (x0 + er < H_IN) ? (x0 + er) : (H_IN - 1);
        const int gy2 = (y0 + ec < W_IN) ? (y0 + ec) : (W_IN - 1);
        ve = __ldg(&inb[gx * W_IN + gy2]);
    }

    // ---- Weight trig (4 threads), same barrier ----
    if (tid < 4) {
        float s, c;
        __sincosf(__ldg(&w[tid]), &s, &c);
        wtrig[tid] = c;
        wtrig[4 + tid] = s;
    }

    // ---- Trig + STS (loads already in flight / landed) ----
    #pragma unroll
    for (int it = 0; it < 4; it++) {
        float s, c;
        __sincosf(v[it] * PI_F, &s, &c);
        CS[wg + 8 * it][lane] = make_float2(c, s);
    }
    if (extra) {
        float s, c;
        __sincosf(ve * PI_F, &s, &c);
        CS[er][ec] = make_float2(c, s);
    }
    __syncthreads();

    // ---- Consumer: R3 verbatim (row-major, lane -> consecutive y) ----
    const int ty = lane;
    const int y = y0 + ty;
    if (y >= L_OUT) return;

    const float cw0 = wtrig[0], cw1 = wtrig[1], cw2 = wtrig[2], cw3 = wtrig[3];
    const float sw0 = wtrig[4], sw1 = wtrig[5], sw2 = wtrig[6], sw3 = wtrig[7];

    const size_t plane = (size_t)L_OUT * L_OUT;
    float* o = out + (size_t)b * 4 * plane + (size_t)(x0 + wg) * L_OUT + y;

    #pragma unroll
    for (int k = 0; k < 4; k++) {
        const int rx = wg + 8 * k;
        if (x0 + rx < L_OUT) {
            const float2 a00 = CS[rx    ][ty    ];
            const float2 a01 = CS[rx    ][ty + 1];
            const float2 a10 = CS[rx + 1][ty    ];
            const float2 a11 = CS[rx + 1][ty + 1];

            const float Z0 = fmaf(-a00.y, sw0, a00.x * cw0);
            const float Z1 = fmaf(-a01.y, sw1, a01.x * cw1);
            const float Z2 = fmaf(-a10.y, sw2, a10.x * cw2);
            const float Z3 = fmaf(-a11.y, sw3, a11.x * cw3);

            const float p01 = Z0 * Z1;
            const float p23 = Z2 * Z3;

            o[0]         = Z1 * p23;    // ch0 = Z1 Z2 Z3
            o[plane]     = p01;         // ch1 = Z0 Z1
            o[2 * plane] = p01 * Z2;    // ch2 = Z0 Z1 Z2
            o[3 * plane] = p01 * p23;   // ch3 = Z0 Z1 Z2 Z3
        }
        o += 8 * L_OUT;
    }
}

extern "C" void kernel_launch(void* const* d_in, const int* in_sizes, int n_in,
                              void* d_out, int out_size) {
    const float* inputs = (const float*)d_in[0];   // (64,1,224,224) float32
    const float* weight = (const float*)d_in[1];   // (1,4) float32
    float* out = (float*)d_out;                    // (64,4,223,223) float32

    dim3 grid((L_OUT + TILE - 1) / TILE,   // 7
              (L_OUT + TILE - 1) / TILE,   // 7
              64);                          // batch
    quanv_main_kernel<<<grid, 256>>>(inputs, weight, out);
}